// round 3
// baseline (speedup 1.0000x reference)
#include <cuda_runtime.h>
#include <cuda_bf16.h>

// Summarizer: logits[b,n] = dot(encoded[b, cls_idx[b,n], :H], W) + bias
// B=32, S=4096, H=768, N=128  -> 4096 independent 768-dot-products.
// One warp per (b,n). Each lane: 6 float4 loads (768 floats / 32 lanes / 4),
// FMA vs W, then warp shuffle reduction.

#ifndef SUM_B
#define SUM_B 32
#define SUM_S 4096
#define SUM_H 768
#define SUM_N 128
#endif

__global__ __launch_bounds__(256) void summarizer_kernel(
    const float* __restrict__ enc,   // [B, S, H]
    const int*   __restrict__ idx,   // [B, N]
    const float* __restrict__ W,     // [H, 1]
    const float* __restrict__ bias,  // [1]
    float*       __restrict__ out)   // [B, N]
{
    const int gwarp = (blockIdx.x * blockDim.x + threadIdx.x) >> 5;
    const int lane  = threadIdx.x & 31;
    if (gwarp >= SUM_B * SUM_N) return;

    const int b = gwarp >> 7;        // /128  (N == 128)
    const int s = __ldg(&idx[gwarp]);        // idx is [B*N] flat

    const float4* row = reinterpret_cast<const float4*>(
        enc + ((size_t)b * SUM_S + (size_t)s) * SUM_H);
    const float4* w4 = reinterpret_cast<const float4*>(W);

    float acc = 0.0f;
#pragma unroll
    for (int i = 0; i < 6; ++i) {           // 6 * 32 lanes * 4 floats = 768
        const int j = i * 32 + lane;
        float4 a = row[j];                  // coalesced 128B per warp-chunk
        float4 w = __ldg(&w4[j]);           // L2-resident after first touch
        acc = fmaf(a.x, w.x, acc);
        acc = fmaf(a.y, w.y, acc);
        acc = fmaf(a.z, w.z, acc);
        acc = fmaf(a.w, w.w, acc);
    }

#pragma unroll
    for (int off = 16; off > 0; off >>= 1)
        acc += __shfl_xor_sync(0xFFFFFFFFu, acc, off);

    if (lane == 0)
        out[gwarp] = acc + __ldg(bias);
}

extern "C" void kernel_launch(void* const* d_in, const int* in_sizes, int n_in,
                              void* d_out, int out_size) {
    const float* enc  = (const float*)d_in[0];  // encoded_output [32,4096,768] f32
    const int*   idx  = (const int*)  d_in[1];  // cls_idx        [32,128] i32
    const float* W    = (const float*)d_in[2];  // W              [768,1] f32
    const float* bias = (const float*)d_in[3];  // b              [1] f32
    float* out = (float*)d_out;                 // logits         [32,128] f32

    const int total_warps = SUM_B * SUM_N;          // 4096
    const int threads = 256;                         // 8 warps / block
    const int blocks  = (total_warps * 32 + threads - 1) / threads;  // 512
    summarizer_kernel<<<blocks, threads>>>(enc, idx, W, bias, out);
}

// round 6
// speedup vs baseline: 1.0048x; 1.0048x over previous
#include <cuda_runtime.h>
#include <cuda_bf16.h>

// Summarizer: logits[b,n] = dot(encoded[b, cls_idx[b,n], :H], W) + bias
// B=32, S=4096, H=768, N=128 -> 4096 independent 768-dot-products.
//
// R4: split each row across TWO warps (half-row = 3 float4 loads/lane) to
// double warp-level parallelism (4096 -> 8192 warps, ~55 warps/SM) and halve
// the per-warp load-latency chain. Partials combined in shared memory.
// Block = 256 threads = 8 warps = 4 outputs; grid = 1024 blocks.

#define SUM_B 32
#define SUM_S 4096
#define SUM_H 768
#define SUM_N 128
#define HALF_F4 96   // (768/4) float4s per row / 2 halves

__global__ __launch_bounds__(256) void summarizer_kernel(
    const float* __restrict__ enc,   // [B, S, H]
    const int*   __restrict__ idx,   // [B*N]
    const float* __restrict__ W,     // [H]
    const float* __restrict__ bias,  // [1]
    float*       __restrict__ out)   // [B*N]
{
    __shared__ float partial[8];

    const int warp = threadIdx.x >> 5;   // 0..7
    const int lane = threadIdx.x & 31;
    const int olocal = warp >> 1;        // 0..3 : output within block
    const int half   = warp & 1;         // 0/1  : which half of the row

    const int gout = (blockIdx.x << 2) + olocal;   // 0..4095
    const int b = gout >> 7;                       // / N (N==128)
    const int s = __ldg(&idx[gout]);

    const float4* row = reinterpret_cast<const float4*>(
        enc + ((size_t)b * SUM_S + (size_t)s) * SUM_H) + half * HALF_F4;
    const float4* w4 = reinterpret_cast<const float4*>(W) + half * HALF_F4;

    float acc = 0.0f;
#pragma unroll
    for (int i = 0; i < 3; ++i) {        // 3 * 32 lanes * 4 floats = 384 = H/2
        const int j = i * 32 + lane;
        float4 a = row[j];               // coalesced, 4x128B lines per LDG
        float4 w = __ldg(&w4[j]);        // L1/L2 resident
        acc = fmaf(a.x, w.x, acc);
        acc = fmaf(a.y, w.y, acc);
        acc = fmaf(a.z, w.z, acc);
        acc = fmaf(a.w, w.w, acc);
    }

#pragma unroll
    for (int off = 16; off > 0; off >>= 1)
        acc += __shfl_xor_sync(0xFFFFFFFFu, acc, off);

    if (lane == 0) partial[warp] = acc;
    __syncthreads();

    if (threadIdx.x < 4) {
        out[(blockIdx.x << 2) + threadIdx.x] =
            partial[2 * threadIdx.x] + partial[2 * threadIdx.x + 1] + __ldg(bias);
    }
}

extern "C" void kernel_launch(void* const* d_in, const int* in_sizes, int n_in,
                              void* d_out, int out_size) {
    const float* enc  = (const float*)d_in[0];  // encoded_output [32,4096,768] f32
    const int*   idx  = (const int*)  d_in[1];  // cls_idx        [32,128] i32
    const float* W    = (const float*)d_in[2];  // W              [768,1] f32
    const float* bias = (const float*)d_in[3];  // b              [1] f32
    float* out = (float*)d_out;                 // logits         [32,128] f32

    const int blocks = (SUM_B * SUM_N) / 4;     // 1024 blocks, 4 outputs each
    summarizer_kernel<<<blocks, 256>>>(enc, idx, W, bias, out);
}